// round 2
// baseline (speedup 1.0000x reference)
#include <cuda_runtime.h>
#include <math.h>

#define NU 50000
#define NI 100000
#define NN 150000
#define D  64
#define NINT 128
#define NE 3000000
#define NL 2

// ---------------- scratch (device globals) ----------------------------------
__device__ __align__(256) float d_embA[NN * D];
__device__ __align__(256) float d_embB[NN * D];
__device__ __align__(256) float d_gnn[NN * D];
__device__ __align__(256) float d_int[NN * D];
__device__ __align__(256) float d_dis[NN];
__device__ __align__(256) float d_invn_g[NN];
__device__ __align__(256) float d_invn_i[NN];
__device__ __align__(256) int   d_cnt[NN];
__device__ __align__(256) int   d_rowptr[NN + 1];
__device__ __align__(256) int   d_fill[NN];
__device__ __align__(256) int   d_csr_t[NE];
__device__ __align__(256) float2 d_alpha[NE];

// ---------------------------------------------------------------------------
__global__ void k_init(const float* __restrict__ ue, const float* __restrict__ ie,
                       float* __restrict__ out) {
    int i = blockIdx.x * blockDim.x + threadIdx.x;
    const int n4  = NN * D / 4;
    const int nu4 = NU * D / 4;
    if (i >= n4) return;
    float4 v = (i < nu4) ? ((const float4*)ue)[i] : ((const float4*)ie)[i - nu4];
    ((float4*)d_embA)[i] = v;
    ((float4*)out)[i]    = v;
}

__global__ void k_cnt_zero() {
    int i = blockIdx.x * blockDim.x + threadIdx.x;
    if (i < NN) d_cnt[i] = 0;
}

__global__ void k_cnt(const int* __restrict__ h) {
    int e = blockIdx.x * blockDim.x + threadIdx.x;
    if (e < NE) atomicAdd(&d_cnt[h[e]], 1);
}

// single-block scan over NN counters -> rowptr ; also dis = deg^-1/2, fill = 0
__global__ void k_scan() {
    __shared__ int ssum[1024];
    const int CH = (NN + 1023) / 1024;   // 147
    int tid = threadIdx.x;
    int beg = tid * CH;
    int end = min(beg + CH, NN);
    int s = 0;
    for (int i = beg; i < end; i++) s += d_cnt[i];
    ssum[tid] = s;
    __syncthreads();
    for (int off = 1; off < 1024; off <<= 1) {
        int v = (tid >= off) ? ssum[tid - off] : 0;
        __syncthreads();
        ssum[tid] += v;
        __syncthreads();
    }
    int run = (tid > 0) ? ssum[tid - 1] : 0;
    for (int i = beg; i < end; i++) {
        d_rowptr[i] = run;
        int c = d_cnt[i];
        run += c;
        d_dis[i]  = (c > 0) ? rsqrtf((float)c) : 0.0f;
        d_fill[i] = 0;
    }
    if (tid == 1023) d_rowptr[NN] = run;
}

__global__ void k_csr(const int* __restrict__ h, const int* __restrict__ t) {
    int e = blockIdx.x * blockDim.x + threadIdx.x;
    if (e >= NE) return;
    int hh = h[e];
    int pos = d_rowptr[hh] + atomicAdd(&d_fill[hh], 1);
    d_csr_t[pos] = t[e];
}

// warp per node: gnn[n] = sum_t dis[n]*dis[t]*emb[t] ; fused inv-norm of gnn row
__global__ void k_spmm_gnn(const float* __restrict__ cur) {
    int n = (blockIdx.x * blockDim.x + threadIdx.x) >> 5;
    int lane = threadIdx.x & 31;
    if (n >= NN) return;
    float dh = d_dis[n];
    float acc0 = 0.f, acc1 = 0.f;
    int b = d_rowptr[n], e = d_rowptr[n + 1];
    for (int i = b; i < e; i++) {
        int tt = __ldg(&d_csr_t[i]);
        float val = dh * __ldg(&d_dis[tt]);
        acc0 += val * __ldg(cur + tt * D + lane);
        acc1 += val * __ldg(cur + tt * D + lane + 32);
    }
    d_gnn[n * D + lane]      = acc0;
    d_gnn[n * D + lane + 32] = acc1;
    float sg = acc0 * acc0 + acc1 * acc1;
    #pragma unroll
    for (int o = 16; o >= 1; o >>= 1) sg += __shfl_xor_sync(0xffffffffu, sg, o);
    if (lane == 0) d_invn_g[n] = 1.0f / fmaxf(sqrtf(sg), 1e-8f);
}

// warp-per-row softmax-intent projection + fused inv-norm of int row
__global__ void k_intent(const float* __restrict__ cur,
                         const float* __restrict__ uW, const float* __restrict__ iW) {
    __shared__ float WT[NINT][D + 1];
    __shared__ float rowbuf[8][D];
    int wid = threadIdx.x >> 5, lane = threadIdx.x & 31;
    int row0 = blockIdx.x * 8;
    const float* W = (row0 < NU) ? uW : iW;
    for (int idx = threadIdx.x; idx < D * NINT; idx += blockDim.x) {
        int dd = idx / NINT, j = idx % NINT;
        WT[j][dd] = W[idx];
    }
    __syncthreads();
    int row = row0 + wid;
    if (row >= NN) return;
    const float* src = cur + row * D;
    rowbuf[wid][lane]      = src[lane];
    rowbuf[wid][lane + 32] = src[lane + 32];
    __syncwarp();

    float lg[4] = {0.f, 0.f, 0.f, 0.f};
    #pragma unroll
    for (int dd = 0; dd < D; dd++) {
        float rb = rowbuf[wid][dd];
        #pragma unroll
        for (int s = 0; s < 4; s++) lg[s] += rb * WT[s * 32 + lane][dd];
    }
    float m = fmaxf(fmaxf(lg[0], lg[1]), fmaxf(lg[2], lg[3]));
    #pragma unroll
    for (int o = 16; o >= 1; o >>= 1) m = fmaxf(m, __shfl_xor_sync(0xffffffffu, m, o));
    float p[4], ssum = 0.f;
    #pragma unroll
    for (int s = 0; s < 4; s++) { p[s] = expf(lg[s] - m); ssum += p[s]; }
    #pragma unroll
    for (int o = 16; o >= 1; o >>= 1) ssum += __shfl_xor_sync(0xffffffffu, ssum, o);
    float inv = 1.0f / ssum;
    #pragma unroll
    for (int s = 0; s < 4; s++) p[s] *= inv;

    float o0 = 0.f, o1 = 0.f;
    #pragma unroll
    for (int s = 0; s < 4; s++) {
        #pragma unroll
        for (int l = 0; l < 32; l++) {
            float pv = __shfl_sync(0xffffffffu, p[s], l);
            int j = s * 32 + l;
            o0 += pv * WT[j][lane];
            o1 += pv * WT[j][lane + 32];
        }
    }
    d_int[row * D + lane]      = o0;
    d_int[row * D + lane + 32] = o1;
    float si = o0 * o0 + o1 * o1;
    #pragma unroll
    for (int o = 16; o >= 1; o >>= 1) si += __shfl_xor_sync(0xffffffffu, si, o);
    if (lane == 0) d_invn_i[row] = 1.0f / fmaxf(sqrtf(si), 1e-8f);
}

// fused: per-edge alphas (both sources) + row-sum + adaptive SpMM + layer epilogue
//   newe[n] = gnn[n] + int[n] + (gaa+iaa)[n] + cur[n] ;  out[n] += newe[n]
__global__ void k_adaptive(const float* __restrict__ cur, float* __restrict__ newe,
                           float* __restrict__ out) {
    int n = (blockIdx.x * blockDim.x + threadIdx.x) >> 5;
    int lane = threadIdx.x & 31;
    if (n >= NN) return;
    int b = d_rowptr[n], e = d_rowptr[n + 1];

    float gh0 = d_gnn[n * D + lane], gh1 = d_gnn[n * D + lane + 32];
    float ih0 = d_int[n * D + lane], ih1 = d_int[n * D + lane + 32];
    float ng = d_invn_g[n], ni = d_invn_i[n];

    float rsg = 0.f, rsi = 0.f;
    for (int i = b; i < e; i++) {
        int tt = __ldg(&d_csr_t[i]);
        float g  = gh0 * __ldg(d_gnn + tt * D + lane) + gh1 * __ldg(d_gnn + tt * D + lane + 32);
        float ii = ih0 * __ldg(d_int + tt * D + lane) + ih1 * __ldg(d_int + tt * D + lane + 32);
        #pragma unroll
        for (int o = 16; o >= 1; o >>= 1) {
            g  += __shfl_xor_sync(0xffffffffu, g, o);
            ii += __shfl_xor_sync(0xffffffffu, ii, o);
        }
        float ag = (g  * ng * __ldg(&d_invn_g[tt]) + 1.0f) * 0.5f;
        float ai = (ii * ni * __ldg(&d_invn_i[tt]) + 1.0f) * 0.5f;
        rsg += ag;
        rsi += ai;
        if (lane == 0) d_alpha[i] = make_float2(ag, ai);
    }
    float dg = (rsg > 0.f) ? (1.0f / rsg) : 0.f;
    float di = (rsi > 0.f) ? (1.0f / rsi) : 0.f;

    float acc0 = 0.f, acc1 = 0.f;
    for (int i = b; i < e; i++) {
        int tt = __ldg(&d_csr_t[i]);
        float2 a = __ldg(&d_alpha[i]);
        float val = dg * a.x + di * a.y;
        acc0 += val * __ldg(cur + tt * D + lane);
        acc1 += val * __ldg(cur + tt * D + lane + 32);
    }

    float e0 = cur[n * D + lane], e1 = cur[n * D + lane + 32];
    float n0 = gh0 + ih0 + acc0 + e0;
    float n1 = gh1 + ih1 + acc1 + e1;
    newe[n * D + lane]      = n0;
    newe[n * D + lane + 32] = n1;
    out[n * D + lane]      += n0;
    out[n * D + lane + 32] += n1;
}

// ---------------------------------------------------------------------------
extern "C" void kernel_launch(void* const* d_in, const int* in_sizes, int n_in,
                              void* d_out, int out_size) {
    const float* ue = (const float*)d_in[0];
    const float* ie = (const float*)d_in[1];
    const float* uW = (const float*)d_in[2];
    const float* iW = (const float*)d_in[3];
    const int*   h  = (const int*)d_in[4];
    const int*   t  = (const int*)d_in[5];
    float* out = (float*)d_out;

    const int TB = 256;
    const int n4   = NN * D / 4;
    const int gN4  = (n4 + TB - 1) / TB;
    const int gNN  = (NN + TB - 1) / TB;
    const int gE   = (NE + TB - 1) / TB;
    const int gNW  = (NN * 32 + TB - 1) / TB;   // warp-per-node

    float *embA, *embB;
    cudaGetSymbolAddress((void**)&embA, d_embA);
    cudaGetSymbolAddress((void**)&embB, d_embB);

    k_init<<<gN4, TB>>>(ue, ie, out);
    k_cnt_zero<<<gNN, TB>>>();
    k_cnt<<<gE, TB>>>(h);
    k_scan<<<1, 1024>>>();
    k_csr<<<gE, TB>>>(h, t);

    float* cur = embA;
    float* nxt = embB;
    for (int layer = 0; layer < NL; layer++) {
        k_spmm_gnn<<<gNW, TB>>>(cur);
        k_intent<<<NN / 8, TB>>>(cur, uW, iW);
        k_adaptive<<<gNW, TB>>>(cur, nxt, out);
        float* tmp = cur; cur = nxt; nxt = tmp;
    }
}

// round 3
// speedup vs baseline: 1.2618x; 1.2618x over previous
#include <cuda_runtime.h>
#include <math.h>

#define NU 50000
#define NI 100000
#define NN 150000
#define D  64
#define NINT 128
#define NE 3000000
#define NL 2
#define SCAN_TB 256
#define NBLK ((NN + SCAN_TB - 1) / SCAN_TB)   // 586

// ---------------- scratch (device globals) ----------------------------------
__device__ __align__(256) float d_embA[NN * D];
__device__ __align__(256) float d_embB[NN * D];
__device__ __align__(256) float d_gnn[NN * D];
__device__ __align__(256) float d_int[NN * D];
__device__ __align__(256) float d_dis[NN];
__device__ __align__(256) float d_invn_g[NN];
__device__ __align__(256) float d_invn_i[NN];
__device__ __align__(256) int   d_cnt[NN];
__device__ __align__(256) int   d_rowptr[NN + 1];
__device__ __align__(256) int   d_fill[NN];
__device__ __align__(256) int   d_csr_t[NE];
__device__ __align__(256) int   d_blksum[NBLK];

// ---------------------------------------------------------------------------
__global__ void k_init(const float* __restrict__ ue, const float* __restrict__ ie,
                       float* __restrict__ out) {
    int i = blockIdx.x * blockDim.x + threadIdx.x;
    const int n4  = NN * D / 4;
    const int nu4 = NU * D / 4;
    if (i >= n4) return;
    float4 v = (i < nu4) ? ((const float4*)ue)[i] : ((const float4*)ie)[i - nu4];
    ((float4*)d_embA)[i] = v;
    ((float4*)out)[i]    = v;
}

__global__ void k_cnt_zero() {
    int i = blockIdx.x * blockDim.x + threadIdx.x;
    if (i < NN) d_cnt[i] = 0;
}

__global__ void k_cnt(const int* __restrict__ h) {
    int e = blockIdx.x * blockDim.x + threadIdx.x;
    if (e < NE) atomicAdd(&d_cnt[h[e]], 1);
}

// per-block sums of counts
__global__ void k_blocksum() {
    __shared__ int sh[SCAN_TB];
    int i = blockIdx.x * SCAN_TB + threadIdx.x;
    int v = (i < NN) ? d_cnt[i] : 0;
    sh[threadIdx.x] = v;
    __syncthreads();
    for (int off = SCAN_TB / 2; off > 0; off >>= 1) {
        if (threadIdx.x < off) sh[threadIdx.x] += sh[threadIdx.x + off];
        __syncthreads();
    }
    if (threadIdx.x == 0) d_blksum[blockIdx.x] = sh[0];
}

// one block: exclusive scan of NBLK block sums (Hillis-Steele in shared)
__global__ void k_scanblk() {
    __shared__ int sh[1024];
    int tid = threadIdx.x;
    sh[tid] = (tid < NBLK) ? d_blksum[tid] : 0;
    __syncthreads();
    for (int off = 1; off < 1024; off <<= 1) {
        int v = (tid >= off) ? sh[tid - off] : 0;
        __syncthreads();
        sh[tid] += v;
        __syncthreads();
    }
    if (tid < NBLK) d_blksum[tid] = (tid > 0) ? sh[tid - 1] : 0;   // exclusive
    if (tid == 0) d_rowptr[NN] = sh[1023];
}

// per-block local exclusive scan + global offset -> rowptr ; dis ; fill=0
__global__ void k_rowptr() {
    __shared__ int sh[SCAN_TB];
    int i = blockIdx.x * SCAN_TB + threadIdx.x;
    int c = (i < NN) ? d_cnt[i] : 0;
    sh[threadIdx.x] = c;
    __syncthreads();
    for (int off = 1; off < SCAN_TB; off <<= 1) {
        int v = (threadIdx.x >= off) ? sh[threadIdx.x - off] : 0;
        __syncthreads();
        sh[threadIdx.x] += v;
        __syncthreads();
    }
    if (i < NN) {
        int excl = sh[threadIdx.x] - c + d_blksum[blockIdx.x];
        d_rowptr[i] = excl;
        d_dis[i]  = (c > 0) ? rsqrtf((float)c) : 0.0f;
        d_fill[i] = 0;
    }
}

__global__ void k_csr(const int* __restrict__ h, const int* __restrict__ t) {
    int e = blockIdx.x * blockDim.x + threadIdx.x;
    if (e >= NE) return;
    int hh = h[e];
    int pos = d_rowptr[hh] + atomicAdd(&d_fill[hh], 1);
    d_csr_t[pos] = t[e];
}

// warp per node: gnn[n] = sum_t dis[n]*dis[t]*emb[t] ; fused inv-norm of gnn row
__global__ void k_spmm_gnn(const float* __restrict__ cur) {
    int n = (blockIdx.x * blockDim.x + threadIdx.x) >> 5;
    int lane = threadIdx.x & 31;
    if (n >= NN) return;
    float dh = d_dis[n];
    float2 acc = make_float2(0.f, 0.f);
    int b = d_rowptr[n], e = d_rowptr[n + 1];
    for (int i = b; i < e; i++) {
        int tt = __ldg(&d_csr_t[i]);
        float val = dh * __ldg(&d_dis[tt]);
        float2 v = __ldg((const float2*)(cur + tt * D) + lane);
        acc.x += val * v.x;
        acc.y += val * v.y;
    }
    ((float2*)(d_gnn + n * D))[lane] = acc;
    float sg = acc.x * acc.x + acc.y * acc.y;
    #pragma unroll
    for (int o = 16; o >= 1; o >>= 1) sg += __shfl_xor_sync(0xffffffffu, sg, o);
    if (lane == 0) d_invn_g[n] = 1.0f / fmaxf(sqrtf(sg), 1e-8f);
}

// warp-per-row softmax-intent projection + fused inv-norm of int row
__global__ void k_intent(const float* __restrict__ cur,
                         const float* __restrict__ uW, const float* __restrict__ iW) {
    __shared__ float WT[NINT][D + 1];
    __shared__ float rowbuf[8][D];
    int wid = threadIdx.x >> 5, lane = threadIdx.x & 31;
    int row0 = blockIdx.x * 8;
    const float* W = (row0 < NU) ? uW : iW;
    for (int idx = threadIdx.x; idx < D * NINT; idx += blockDim.x) {
        int dd = idx / NINT, j = idx % NINT;
        WT[j][dd] = W[idx];
    }
    __syncthreads();
    int row = row0 + wid;
    if (row >= NN) return;
    const float* src = cur + row * D;
    rowbuf[wid][lane]      = src[lane];
    rowbuf[wid][lane + 32] = src[lane + 32];
    __syncwarp();

    float lg[4] = {0.f, 0.f, 0.f, 0.f};
    #pragma unroll
    for (int dd = 0; dd < D; dd++) {
        float rb = rowbuf[wid][dd];
        #pragma unroll
        for (int s = 0; s < 4; s++) lg[s] += rb * WT[s * 32 + lane][dd];
    }
    float m = fmaxf(fmaxf(lg[0], lg[1]), fmaxf(lg[2], lg[3]));
    #pragma unroll
    for (int o = 16; o >= 1; o >>= 1) m = fmaxf(m, __shfl_xor_sync(0xffffffffu, m, o));
    float p[4], ssum = 0.f;
    #pragma unroll
    for (int s = 0; s < 4; s++) { p[s] = expf(lg[s] - m); ssum += p[s]; }
    #pragma unroll
    for (int o = 16; o >= 1; o >>= 1) ssum += __shfl_xor_sync(0xffffffffu, ssum, o);
    float inv = 1.0f / ssum;
    #pragma unroll
    for (int s = 0; s < 4; s++) p[s] *= inv;

    float o0 = 0.f, o1 = 0.f;
    #pragma unroll
    for (int s = 0; s < 4; s++) {
        #pragma unroll
        for (int l = 0; l < 32; l++) {
            float pv = __shfl_sync(0xffffffffu, p[s], l);
            int j = s * 32 + l;
            o0 += pv * WT[j][lane];
            o1 += pv * WT[j][lane + 32];
        }
    }
    d_int[row * D + lane]      = o0;
    d_int[row * D + lane + 32] = o1;
    float si = o0 * o0 + o1 * o1;
    #pragma unroll
    for (int o = 16; o >= 1; o >>= 1) si += __shfl_xor_sync(0xffffffffu, si, o);
    if (lane == 0) d_invn_i[row] = 1.0f / fmaxf(sqrtf(si), 1e-8f);
}

// fully fused adaptive pass, warp per node, single edge loop:
//   per edge: ag, ai (cosine alphas) ; rsg += ag ; rsi += ai ;
//             accg += ag*emb[t] ; acci += ai*emb[t]
//   epilogue: newe = gnn + int + dg*accg + di*acci + cur ; out += newe
__global__ void k_adaptive(const float* __restrict__ cur, float* __restrict__ newe,
                           float* __restrict__ out) {
    int n = (blockIdx.x * blockDim.x + threadIdx.x) >> 5;
    int lane = threadIdx.x & 31;
    if (n >= NN) return;
    int b = d_rowptr[n], e = d_rowptr[n + 1];

    float2 gh = ((const float2*)(d_gnn + n * D))[lane];
    float2 ih = ((const float2*)(d_int + n * D))[lane];
    float ng = d_invn_g[n], ni = d_invn_i[n];

    float rsg = 0.f, rsi = 0.f;
    float2 accg = make_float2(0.f, 0.f), acci = make_float2(0.f, 0.f);
    for (int i = b; i < e; i++) {
        int tt = __ldg(&d_csr_t[i]);
        float2 gt = __ldg((const float2*)(d_gnn + tt * D) + lane);
        float2 it = __ldg((const float2*)(d_int + tt * D) + lane);
        float2 ev = __ldg((const float2*)(cur   + tt * D) + lane);
        float g  = gh.x * gt.x + gh.y * gt.y;
        float ii = ih.x * it.x + ih.y * it.y;
        #pragma unroll
        for (int o = 16; o >= 1; o >>= 1) {
            g  += __shfl_xor_sync(0xffffffffu, g, o);
            ii += __shfl_xor_sync(0xffffffffu, ii, o);
        }
        float ag = (g  * ng * __ldg(&d_invn_g[tt]) + 1.0f) * 0.5f;
        float ai = (ii * ni * __ldg(&d_invn_i[tt]) + 1.0f) * 0.5f;
        rsg += ag;
        rsi += ai;
        accg.x += ag * ev.x;  accg.y += ag * ev.y;
        acci.x += ai * ev.x;  acci.y += ai * ev.y;
    }
    float dg = (rsg > 0.f) ? (1.0f / rsg) : 0.f;
    float di = (rsi > 0.f) ? (1.0f / rsi) : 0.f;

    float2 e0 = ((const float2*)(cur + n * D))[lane];
    float2 nv;
    nv.x = gh.x + ih.x + dg * accg.x + di * acci.x + e0.x;
    nv.y = gh.y + ih.y + dg * accg.y + di * acci.y + e0.y;
    ((float2*)(newe + n * D))[lane] = nv;
    float2 ov = ((float2*)(out + n * D))[lane];
    ov.x += nv.x;
    ov.y += nv.y;
    ((float2*)(out + n * D))[lane] = ov;
}

// ---------------------------------------------------------------------------
extern "C" void kernel_launch(void* const* d_in, const int* in_sizes, int n_in,
                              void* d_out, int out_size) {
    const float* ue = (const float*)d_in[0];
    const float* ie = (const float*)d_in[1];
    const float* uW = (const float*)d_in[2];
    const float* iW = (const float*)d_in[3];
    const int*   h  = (const int*)d_in[4];
    const int*   t  = (const int*)d_in[5];
    float* out = (float*)d_out;

    const int TB = 256;
    const int n4   = NN * D / 4;
    const int gN4  = (n4 + TB - 1) / TB;
    const int gNN  = (NN + TB - 1) / TB;
    const int gE   = (NE + TB - 1) / TB;
    const int gNW  = (NN * 32 + TB - 1) / TB;   // warp-per-node

    float *embA, *embB;
    cudaGetSymbolAddress((void**)&embA, d_embA);
    cudaGetSymbolAddress((void**)&embB, d_embB);

    k_init<<<gN4, TB>>>(ue, ie, out);
    k_cnt_zero<<<gNN, TB>>>();
    k_cnt<<<gE, TB>>>(h);
    k_blocksum<<<NBLK, SCAN_TB>>>();
    k_scanblk<<<1, 1024>>>();
    k_rowptr<<<NBLK, SCAN_TB>>>();
    k_csr<<<gE, TB>>>(h, t);

    float* cur = embA;
    float* nxt = embB;
    for (int layer = 0; layer < NL; layer++) {
        k_spmm_gnn<<<gNW, TB>>>(cur);
        k_intent<<<NN / 8, TB>>>(cur, uW, iW);
        k_adaptive<<<gNW, TB>>>(cur, nxt, out);
        float* tmp = cur; cur = nxt; nxt = tmp;
    }
}

// round 5
// speedup vs baseline: 1.3837x; 1.0966x over previous
#include <cuda_runtime.h>
#include <math.h>

#define NU 50000
#define NI 100000
#define NN 150000
#define D  64
#define NINT 128
#define NE 3000000
#define NL 2
#define SCAN_TB 256
#define NBLK ((NN + SCAN_TB - 1) / SCAN_TB)   // 586

// ---------------- scratch (device globals) ----------------------------------
__device__ __align__(256) float d_embA[NN * D];
__device__ __align__(256) float d_embB[NN * D];
__device__ __align__(256) float d_gnn[NN * D];
__device__ __align__(256) float d_int[NN * D];
__device__ __align__(256) float d_dis[NN];
__device__ __align__(256) float d_invn_g[NN];
__device__ __align__(256) float d_invn_i[NN];
__device__ __align__(256) int   d_cnt[NN];
__device__ __align__(256) int   d_rowptr[NN + 1];
__device__ __align__(256) int   d_fill[NN];
__device__ __align__(256) int   d_csr_t[NE];
__device__ __align__(256) int   d_blksum[NBLK];

// ---------------------------------------------------------------------------
__global__ void k_init(const float* __restrict__ ue, const float* __restrict__ ie,
                       float* __restrict__ out) {
    int i = blockIdx.x * blockDim.x + threadIdx.x;
    const int n4  = NN * D / 4;
    const int nu4 = NU * D / 4;
    if (i >= n4) return;
    float4 v = (i < nu4) ? ((const float4*)ue)[i] : ((const float4*)ie)[i - nu4];
    ((float4*)d_embA)[i] = v;
    ((float4*)out)[i]    = v;
}

__global__ void k_cnt_zero() {
    int i = blockIdx.x * blockDim.x + threadIdx.x;
    if (i < NN) d_cnt[i] = 0;
}

__global__ void k_cnt(const int* __restrict__ h) {
    int e = blockIdx.x * blockDim.x + threadIdx.x;
    if (e < NE) atomicAdd(&d_cnt[h[e]], 1);
}

__global__ void k_blocksum() {
    __shared__ int sh[SCAN_TB];
    int i = blockIdx.x * SCAN_TB + threadIdx.x;
    int v = (i < NN) ? d_cnt[i] : 0;
    sh[threadIdx.x] = v;
    __syncthreads();
    for (int off = SCAN_TB / 2; off > 0; off >>= 1) {
        if (threadIdx.x < off) sh[threadIdx.x] += sh[threadIdx.x + off];
        __syncthreads();
    }
    if (threadIdx.x == 0) d_blksum[blockIdx.x] = sh[0];
}

__global__ void k_scanblk() {
    __shared__ int sh[1024];
    int tid = threadIdx.x;
    sh[tid] = (tid < NBLK) ? d_blksum[tid] : 0;
    __syncthreads();
    for (int off = 1; off < 1024; off <<= 1) {
        int v = (tid >= off) ? sh[tid - off] : 0;
        __syncthreads();
        sh[tid] += v;
        __syncthreads();
    }
    if (tid < NBLK) d_blksum[tid] = (tid > 0) ? sh[tid - 1] : 0;
    if (tid == 0) d_rowptr[NN] = sh[1023];
}

__global__ void k_rowptr() {
    __shared__ int sh[SCAN_TB];
    int i = blockIdx.x * SCAN_TB + threadIdx.x;
    int c = (i < NN) ? d_cnt[i] : 0;
    sh[threadIdx.x] = c;
    __syncthreads();
    for (int off = 1; off < SCAN_TB; off <<= 1) {
        int v = (threadIdx.x >= off) ? sh[threadIdx.x - off] : 0;
        __syncthreads();
        sh[threadIdx.x] += v;
        __syncthreads();
    }
    if (i < NN) {
        int excl = sh[threadIdx.x] - c + d_blksum[blockIdx.x];
        d_rowptr[i] = excl;
        d_dis[i]  = (c > 0) ? rsqrtf((float)c) : 0.0f;
        d_fill[i] = 0;
    }
}

__global__ void k_csr(const int* __restrict__ h, const int* __restrict__ t) {
    int e = blockIdx.x * blockDim.x + threadIdx.x;
    if (e >= NE) return;
    int hh = h[e];
    int pos = d_rowptr[hh] + atomicAdd(&d_fill[hh], 1);
    d_csr_t[pos] = t[e];
}

// warp per node, 16 lanes per edge, 2 edges/iter.
// gnn[n] = sum_t dis[n]*dis[t]*emb[t] ; fused inv-norm of gnn row.
__global__ void k_spmm_gnn(const float* __restrict__ cur) {
    int n = (blockIdx.x * blockDim.x + threadIdx.x) >> 5;
    int lane = threadIdx.x & 31;
    if (n >= NN) return;
    int half = lane >> 4;       // which edge of the pair
    int q    = lane & 15;       // float4 slot within the row
    float dh = d_dis[n];
    float4 acc = make_float4(0.f, 0.f, 0.f, 0.f);
    int b = d_rowptr[n], e = d_rowptr[n + 1];
    for (int i = b + half; i < e; i += 2) {
        int tt = __ldg(&d_csr_t[i]);
        float val = dh * __ldg(&d_dis[tt]);
        float4 v = __ldg((const float4*)(cur + tt * D) + q);
        acc.x += val * v.x; acc.y += val * v.y;
        acc.z += val * v.z; acc.w += val * v.w;
    }
    // combine the two halves (warp reconverged after loop)
    acc.x += __shfl_xor_sync(0xffffffffu, acc.x, 16);
    acc.y += __shfl_xor_sync(0xffffffffu, acc.y, 16);
    acc.z += __shfl_xor_sync(0xffffffffu, acc.z, 16);
    acc.w += __shfl_xor_sync(0xffffffffu, acc.w, 16);
    float sg = acc.x * acc.x + acc.y * acc.y + acc.z * acc.z + acc.w * acc.w;
    #pragma unroll
    for (int o = 8; o >= 1; o >>= 1) sg += __shfl_xor_sync(0xffffffffu, sg, o);
    if (lane == 0) d_invn_g[n] = 1.0f / fmaxf(sqrtf(sg), 1e-8f);
    if (half == 0) ((float4*)(d_gnn + n * D))[q] = acc;
}

// warp-per-row softmax-intent projection + fused inv-norm of int row
__global__ void k_intent(const float* __restrict__ cur,
                         const float* __restrict__ uW, const float* __restrict__ iW) {
    __shared__ float WT[NINT][D + 1];
    __shared__ float rowbuf[8][D];
    int wid = threadIdx.x >> 5, lane = threadIdx.x & 31;
    int row0 = blockIdx.x * 8;
    const float* W = (row0 < NU) ? uW : iW;
    for (int idx = threadIdx.x; idx < D * NINT; idx += blockDim.x) {
        int dd = idx / NINT, j = idx % NINT;
        WT[j][dd] = W[idx];
    }
    __syncthreads();
    int row = row0 + wid;
    if (row >= NN) return;
    const float* src = cur + row * D;
    rowbuf[wid][lane]      = src[lane];
    rowbuf[wid][lane + 32] = src[lane + 32];
    __syncwarp();

    float lg[4] = {0.f, 0.f, 0.f, 0.f};
    #pragma unroll
    for (int dd = 0; dd < D; dd++) {
        float rb = rowbuf[wid][dd];
        #pragma unroll
        for (int s = 0; s < 4; s++) lg[s] += rb * WT[s * 32 + lane][dd];
    }
    float m = fmaxf(fmaxf(lg[0], lg[1]), fmaxf(lg[2], lg[3]));
    #pragma unroll
    for (int o = 16; o >= 1; o >>= 1) m = fmaxf(m, __shfl_xor_sync(0xffffffffu, m, o));
    float p[4], ssum = 0.f;
    #pragma unroll
    for (int s = 0; s < 4; s++) { p[s] = expf(lg[s] - m); ssum += p[s]; }
    #pragma unroll
    for (int o = 16; o >= 1; o >>= 1) ssum += __shfl_xor_sync(0xffffffffu, ssum, o);
    float inv = 1.0f / ssum;
    #pragma unroll
    for (int s = 0; s < 4; s++) p[s] *= inv;

    float o0 = 0.f, o1 = 0.f;
    #pragma unroll
    for (int s = 0; s < 4; s++) {
        #pragma unroll
        for (int l = 0; l < 32; l++) {
            float pv = __shfl_sync(0xffffffffu, p[s], l);
            int j = s * 32 + l;
            o0 += pv * WT[j][lane];
            o1 += pv * WT[j][lane + 32];
        }
    }
    d_int[row * D + lane]      = o0;
    d_int[row * D + lane + 32] = o1;
    float si = o0 * o0 + o1 * o1;
    #pragma unroll
    for (int o = 16; o >= 1; o >>= 1) si += __shfl_xor_sync(0xffffffffu, si, o);
    if (lane == 0) d_invn_i[row] = 1.0f / fmaxf(sqrtf(si), 1e-8f);
}

// fully fused adaptive pass, warp per node, 16 lanes/edge, 2 edges/iter.
// In-loop reductions use HALF-scoped masks: the two halves may have different
// trip counts (odd degree), so full-mask shuffles there would be UB.
__global__ void k_adaptive(const float* __restrict__ cur, float* __restrict__ newe,
                           float* __restrict__ out) {
    int n = (blockIdx.x * blockDim.x + threadIdx.x) >> 5;
    int lane = threadIdx.x & 31;
    if (n >= NN) return;
    int half = lane >> 4;
    int q    = lane & 15;
    unsigned hmask = half ? 0xFFFF0000u : 0x0000FFFFu;
    int b = d_rowptr[n], e = d_rowptr[n + 1];

    float4 gh = __ldg((const float4*)(d_gnn + n * D) + q);
    float4 ih = __ldg((const float4*)(d_int + n * D) + q);
    float ng = d_invn_g[n], ni = d_invn_i[n];

    float rsg = 0.f, rsi = 0.f;
    float4 accg = make_float4(0.f, 0.f, 0.f, 0.f);
    float4 acci = make_float4(0.f, 0.f, 0.f, 0.f);
    for (int i = b + half; i < e; i += 2) {
        int tt = __ldg(&d_csr_t[i]);
        float4 gt = __ldg((const float4*)(d_gnn + tt * D) + q);
        float4 it = __ldg((const float4*)(d_int + tt * D) + q);
        float4 ev = __ldg((const float4*)(cur   + tt * D) + q);
        float g  = gh.x * gt.x + gh.y * gt.y + gh.z * gt.z + gh.w * gt.w;
        float ii = ih.x * it.x + ih.y * it.y + ih.z * it.z + ih.w * it.w;
        #pragma unroll
        for (int o = 8; o >= 1; o >>= 1) {
            g  += __shfl_xor_sync(hmask, g, o);
            ii += __shfl_xor_sync(hmask, ii, o);
        }
        float ag = (g  * ng * __ldg(&d_invn_g[tt]) + 1.0f) * 0.5f;
        float ai = (ii * ni * __ldg(&d_invn_i[tt]) + 1.0f) * 0.5f;
        rsg += ag;
        rsi += ai;
        accg.x += ag * ev.x; accg.y += ag * ev.y;
        accg.z += ag * ev.z; accg.w += ag * ev.w;
        acci.x += ai * ev.x; acci.y += ai * ev.y;
        acci.z += ai * ev.z; acci.w += ai * ev.w;
    }
    // combine halves (warp reconverged after loop)
    rsg += __shfl_xor_sync(0xffffffffu, rsg, 16);
    rsi += __shfl_xor_sync(0xffffffffu, rsi, 16);
    accg.x += __shfl_xor_sync(0xffffffffu, accg.x, 16);
    accg.y += __shfl_xor_sync(0xffffffffu, accg.y, 16);
    accg.z += __shfl_xor_sync(0xffffffffu, accg.z, 16);
    accg.w += __shfl_xor_sync(0xffffffffu, accg.w, 16);
    acci.x += __shfl_xor_sync(0xffffffffu, acci.x, 16);
    acci.y += __shfl_xor_sync(0xffffffffu, acci.y, 16);
    acci.z += __shfl_xor_sync(0xffffffffu, acci.z, 16);
    acci.w += __shfl_xor_sync(0xffffffffu, acci.w, 16);

    float dg = (rsg > 0.f) ? (1.0f / rsg) : 0.f;
    float di = (rsi > 0.f) ? (1.0f / rsi) : 0.f;

    if (half == 0) {
        float4 e0 = __ldg((const float4*)(cur + n * D) + q);
        float4 nv;
        nv.x = gh.x + ih.x + dg * accg.x + di * acci.x + e0.x;
        nv.y = gh.y + ih.y + dg * accg.y + di * acci.y + e0.y;
        nv.z = gh.z + ih.z + dg * accg.z + di * acci.z + e0.z;
        nv.w = gh.w + ih.w + dg * accg.w + di * acci.w + e0.w;
        ((float4*)(newe + n * D))[q] = nv;
        float4 ov = ((float4*)(out + n * D))[q];
        ov.x += nv.x; ov.y += nv.y; ov.z += nv.z; ov.w += nv.w;
        ((float4*)(out + n * D))[q] = ov;
    }
}

// ---------------------------------------------------------------------------
extern "C" void kernel_launch(void* const* d_in, const int* in_sizes, int n_in,
                              void* d_out, int out_size) {
    const float* ue = (const float*)d_in[0];
    const float* ie = (const float*)d_in[1];
    const float* uW = (const float*)d_in[2];
    const float* iW = (const float*)d_in[3];
    const int*   h  = (const int*)d_in[4];
    const int*   t  = (const int*)d_in[5];
    float* out = (float*)d_out;

    const int TB = 256;
    const int n4   = NN * D / 4;
    const int gN4  = (n4 + TB - 1) / TB;
    const int gNN  = (NN + TB - 1) / TB;
    const int gE   = (NE + TB - 1) / TB;
    const int gNW  = (NN * 32 + TB - 1) / TB;   // warp-per-node

    float *embA, *embB;
    cudaGetSymbolAddress((void**)&embA, d_embA);
    cudaGetSymbolAddress((void**)&embB, d_embB);

    k_init<<<gN4, TB>>>(ue, ie, out);
    k_cnt_zero<<<gNN, TB>>>();
    k_cnt<<<gE, TB>>>(h);
    k_blocksum<<<NBLK, SCAN_TB>>>();
    k_scanblk<<<1, 1024>>>();
    k_rowptr<<<NBLK, SCAN_TB>>>();
    k_csr<<<gE, TB>>>(h, t);

    float* cur = embA;
    float* nxt = embB;
    for (int layer = 0; layer < NL; layer++) {
        k_spmm_gnn<<<gNW, TB>>>(cur);
        k_intent<<<NN / 8, TB>>>(cur, uW, iW);
        k_adaptive<<<gNW, TB>>>(cur, nxt, out);
        float* tmp = cur; cur = nxt; nxt = tmp;
    }
}

// round 6
// speedup vs baseline: 1.5161x; 1.0957x over previous
#include <cuda_runtime.h>
#include <math.h>

#define NU 50000
#define NI 100000
#define NN 150000
#define D  64
#define NINT 128
#define NE 3000000
#define NL 2
#define SCAN_TB 256
#define NBLK ((NN + SCAN_TB - 1) / SCAN_TB)   // 586

// ---------------- scratch (device globals) ----------------------------------
__device__ __align__(256) float d_embA[NN * D];
__device__ __align__(256) float d_embB[NN * D];
__device__ __align__(256) float d_gi[NN * 2 * D];   // [n][0:64]=gnn, [n][64:128]=int
__device__ __align__(256) float d_dis[NN];
__device__ __align__(256) float2 d_invn[NN];        // (inv_norm_gnn, inv_norm_int)
__device__ __align__(256) int   d_cnt[NN];
__device__ __align__(256) int   d_rowptr[NN + 1];
__device__ __align__(256) int   d_fill[NN];
__device__ __align__(256) int   d_csr_t[NE];
__device__ __align__(256) int   d_blksum[NBLK];

// ---------------------------------------------------------------------------
__global__ void k_init(const float* __restrict__ ue, const float* __restrict__ ie,
                       float* __restrict__ out) {
    int i = blockIdx.x * blockDim.x + threadIdx.x;
    const int n4  = NN * D / 4;
    const int nu4 = NU * D / 4;
    if (i >= n4) return;
    float4 v = (i < nu4) ? ((const float4*)ue)[i] : ((const float4*)ie)[i - nu4];
    ((float4*)d_embA)[i] = v;
    ((float4*)out)[i]    = v;
}

__global__ void k_cnt_zero() {
    int i = blockIdx.x * blockDim.x + threadIdx.x;
    if (i < NN) d_cnt[i] = 0;
}

__global__ void k_cnt(const int* __restrict__ h) {
    int e = blockIdx.x * blockDim.x + threadIdx.x;
    if (e < NE) atomicAdd(&d_cnt[h[e]], 1);
}

__global__ void k_blocksum() {
    __shared__ int sh[SCAN_TB];
    int i = blockIdx.x * SCAN_TB + threadIdx.x;
    int v = (i < NN) ? d_cnt[i] : 0;
    sh[threadIdx.x] = v;
    __syncthreads();
    for (int off = SCAN_TB / 2; off > 0; off >>= 1) {
        if (threadIdx.x < off) sh[threadIdx.x] += sh[threadIdx.x + off];
        __syncthreads();
    }
    if (threadIdx.x == 0) d_blksum[blockIdx.x] = sh[0];
}

__global__ void k_scanblk() {
    __shared__ int sh[1024];
    int tid = threadIdx.x;
    sh[tid] = (tid < NBLK) ? d_blksum[tid] : 0;
    __syncthreads();
    for (int off = 1; off < 1024; off <<= 1) {
        int v = (tid >= off) ? sh[tid - off] : 0;
        __syncthreads();
        sh[tid] += v;
        __syncthreads();
    }
    if (tid < NBLK) d_blksum[tid] = (tid > 0) ? sh[tid - 1] : 0;
    if (tid == 0) d_rowptr[NN] = sh[1023];
}

__global__ void k_rowptr() {
    __shared__ int sh[SCAN_TB];
    int i = blockIdx.x * SCAN_TB + threadIdx.x;
    int c = (i < NN) ? d_cnt[i] : 0;
    sh[threadIdx.x] = c;
    __syncthreads();
    for (int off = 1; off < SCAN_TB; off <<= 1) {
        int v = (threadIdx.x >= off) ? sh[threadIdx.x - off] : 0;
        __syncthreads();
        sh[threadIdx.x] += v;
        __syncthreads();
    }
    if (i < NN) {
        int excl = sh[threadIdx.x] - c + d_blksum[blockIdx.x];
        d_rowptr[i] = excl;
        d_dis[i]  = (c > 0) ? rsqrtf((float)c) : 0.0f;
        d_fill[i] = 0;
    }
}

__global__ void k_csr(const int* __restrict__ h, const int* __restrict__ t) {
    int e = blockIdx.x * blockDim.x + threadIdx.x;
    if (e >= NE) return;
    int hh = h[e];
    int pos = d_rowptr[hh] + atomicAdd(&d_fill[hh], 1);
    d_csr_t[pos] = t[e];
}

// warp per node, 16 lanes/edge, 2 edges per half-iter (4 edges in flight).
// gnn[n] = sum_t dis[n]*dis[t]*emb[t] ; writes into d_gi[n][0:64] + norm.
__global__ void k_spmm_gnn(const float* __restrict__ cur) {
    int n = (blockIdx.x * blockDim.x + threadIdx.x) >> 5;
    int lane = threadIdx.x & 31;
    if (n >= NN) return;
    int half = lane >> 4;
    int q    = lane & 15;
    float dh = d_dis[n];
    float4 a0 = make_float4(0.f, 0.f, 0.f, 0.f);
    float4 a1 = make_float4(0.f, 0.f, 0.f, 0.f);
    int b = d_rowptr[n], e = d_rowptr[n + 1];
    int i = b + half;
    for (; i + 2 < e; i += 4) {
        int t0 = __ldg(&d_csr_t[i]);
        int t1 = __ldg(&d_csr_t[i + 2]);
        float v0 = dh * __ldg(&d_dis[t0]);
        float v1 = dh * __ldg(&d_dis[t1]);
        float4 r0 = __ldg((const float4*)(cur + t0 * D) + q);
        float4 r1 = __ldg((const float4*)(cur + t1 * D) + q);
        a0.x += v0 * r0.x; a0.y += v0 * r0.y; a0.z += v0 * r0.z; a0.w += v0 * r0.w;
        a1.x += v1 * r1.x; a1.y += v1 * r1.y; a1.z += v1 * r1.z; a1.w += v1 * r1.w;
    }
    for (; i < e; i += 2) {
        int t0 = __ldg(&d_csr_t[i]);
        float v0 = dh * __ldg(&d_dis[t0]);
        float4 r0 = __ldg((const float4*)(cur + t0 * D) + q);
        a0.x += v0 * r0.x; a0.y += v0 * r0.y; a0.z += v0 * r0.z; a0.w += v0 * r0.w;
    }
    a0.x += a1.x; a0.y += a1.y; a0.z += a1.z; a0.w += a1.w;
    a0.x += __shfl_xor_sync(0xffffffffu, a0.x, 16);
    a0.y += __shfl_xor_sync(0xffffffffu, a0.y, 16);
    a0.z += __shfl_xor_sync(0xffffffffu, a0.z, 16);
    a0.w += __shfl_xor_sync(0xffffffffu, a0.w, 16);
    float sg = a0.x * a0.x + a0.y * a0.y + a0.z * a0.z + a0.w * a0.w;
    #pragma unroll
    for (int o = 8; o >= 1; o >>= 1) sg += __shfl_xor_sync(0xffffffffu, sg, o);
    if (lane == 0) d_invn[n].x = 1.0f / fmaxf(sqrtf(sg), 1e-8f);
    if (half == 0) ((float4*)(d_gi + n * 2 * D))[q] = a0;
}

// warp-per-row softmax-intent projection; writes d_gi[n][64:128] + norm.
__global__ void k_intent(const float* __restrict__ cur,
                         const float* __restrict__ uW, const float* __restrict__ iW) {
    __shared__ float WT[NINT][D + 1];
    __shared__ float rowbuf[8][D];
    int wid = threadIdx.x >> 5, lane = threadIdx.x & 31;
    int row0 = blockIdx.x * 8;
    const float* W = (row0 < NU) ? uW : iW;
    for (int idx = threadIdx.x; idx < D * NINT; idx += blockDim.x) {
        int dd = idx / NINT, j = idx % NINT;
        WT[j][dd] = W[idx];
    }
    __syncthreads();
    int row = row0 + wid;
    if (row >= NN) return;
    const float* src = cur + row * D;
    rowbuf[wid][lane]      = src[lane];
    rowbuf[wid][lane + 32] = src[lane + 32];
    __syncwarp();

    float lg[4] = {0.f, 0.f, 0.f, 0.f};
    #pragma unroll
    for (int dd = 0; dd < D; dd++) {
        float rb = rowbuf[wid][dd];
        #pragma unroll
        for (int s = 0; s < 4; s++) lg[s] += rb * WT[s * 32 + lane][dd];
    }
    float m = fmaxf(fmaxf(lg[0], lg[1]), fmaxf(lg[2], lg[3]));
    #pragma unroll
    for (int o = 16; o >= 1; o >>= 1) m = fmaxf(m, __shfl_xor_sync(0xffffffffu, m, o));
    float p[4], ssum = 0.f;
    #pragma unroll
    for (int s = 0; s < 4; s++) { p[s] = expf(lg[s] - m); ssum += p[s]; }
    #pragma unroll
    for (int o = 16; o >= 1; o >>= 1) ssum += __shfl_xor_sync(0xffffffffu, ssum, o);
    float inv = 1.0f / ssum;
    #pragma unroll
    for (int s = 0; s < 4; s++) p[s] *= inv;

    float o0 = 0.f, o1 = 0.f;
    #pragma unroll
    for (int s = 0; s < 4; s++) {
        #pragma unroll
        for (int l = 0; l < 32; l++) {
            float pv = __shfl_sync(0xffffffffu, p[s], l);
            int j = s * 32 + l;
            o0 += pv * WT[j][lane];
            o1 += pv * WT[j][lane + 32];
        }
    }
    d_gi[row * 2 * D + D + lane]      = o0;
    d_gi[row * 2 * D + D + lane + 32] = o1;
    float si = o0 * o0 + o1 * o1;
    #pragma unroll
    for (int o = 16; o >= 1; o >>= 1) si += __shfl_xor_sync(0xffffffffu, si, o);
    if (lane == 0) d_invn[row].y = 1.0f / fmaxf(sqrtf(si), 1e-8f);
}

// fused adaptive pass, warp per node, 16 lanes/edge, unrolled 2x per half
// (4 edges in flight). Half-scoped masks for in-loop reductions.
__global__ void k_adaptive(const float* __restrict__ cur, float* __restrict__ newe,
                           float* __restrict__ out) {
    int n = (blockIdx.x * blockDim.x + threadIdx.x) >> 5;
    int lane = threadIdx.x & 31;
    if (n >= NN) return;
    int half = lane >> 4;
    int q    = lane & 15;
    unsigned hmask = half ? 0xFFFF0000u : 0x0000FFFFu;
    int b = d_rowptr[n], e = d_rowptr[n + 1];

    const float4* gi = (const float4*)(d_gi + n * 2 * D);
    float4 gh = __ldg(gi + q);
    float4 ih = __ldg(gi + 16 + q);
    float2 nn = d_invn[n];
    float ng = nn.x, ni = nn.y;

    float rsg = 0.f, rsi = 0.f;
    float4 accg = make_float4(0.f, 0.f, 0.f, 0.f);
    float4 acci = make_float4(0.f, 0.f, 0.f, 0.f);

    int i = b + half;
    for (; i + 2 < e; i += 4) {
        int t0 = __ldg(&d_csr_t[i]);
        int t1 = __ldg(&d_csr_t[i + 2]);
        const float4* p0 = (const float4*)(d_gi + t0 * 2 * D);
        const float4* p1 = (const float4*)(d_gi + t1 * 2 * D);
        float4 gt0 = __ldg(p0 + q);
        float4 it0 = __ldg(p0 + 16 + q);
        float4 gt1 = __ldg(p1 + q);
        float4 it1 = __ldg(p1 + 16 + q);
        float4 ev0 = __ldg((const float4*)(cur + t0 * D) + q);
        float4 ev1 = __ldg((const float4*)(cur + t1 * D) + q);
        float2 n0 = __ldg(&d_invn[t0]);
        float2 n1 = __ldg(&d_invn[t1]);

        float g0  = gh.x * gt0.x + gh.y * gt0.y + gh.z * gt0.z + gh.w * gt0.w;
        float i0  = ih.x * it0.x + ih.y * it0.y + ih.z * it0.z + ih.w * it0.w;
        float g1  = gh.x * gt1.x + gh.y * gt1.y + gh.z * gt1.z + gh.w * gt1.w;
        float i1  = ih.x * it1.x + ih.y * it1.y + ih.z * it1.z + ih.w * it1.w;
        #pragma unroll
        for (int o = 8; o >= 1; o >>= 1) {
            g0 += __shfl_xor_sync(hmask, g0, o);
            i0 += __shfl_xor_sync(hmask, i0, o);
            g1 += __shfl_xor_sync(hmask, g1, o);
            i1 += __shfl_xor_sync(hmask, i1, o);
        }
        float ag0 = (g0 * ng * n0.x + 1.0f) * 0.5f;
        float ai0 = (i0 * ni * n0.y + 1.0f) * 0.5f;
        float ag1 = (g1 * ng * n1.x + 1.0f) * 0.5f;
        float ai1 = (i1 * ni * n1.y + 1.0f) * 0.5f;
        rsg += ag0 + ag1;
        rsi += ai0 + ai1;
        accg.x += ag0 * ev0.x + ag1 * ev1.x;
        accg.y += ag0 * ev0.y + ag1 * ev1.y;
        accg.z += ag0 * ev0.z + ag1 * ev1.z;
        accg.w += ag0 * ev0.w + ag1 * ev1.w;
        acci.x += ai0 * ev0.x + ai1 * ev1.x;
        acci.y += ai0 * ev0.y + ai1 * ev1.y;
        acci.z += ai0 * ev0.z + ai1 * ev1.z;
        acci.w += ai0 * ev0.w + ai1 * ev1.w;
    }
    for (; i < e; i += 2) {
        int t0 = __ldg(&d_csr_t[i]);
        const float4* p0 = (const float4*)(d_gi + t0 * 2 * D);
        float4 gt0 = __ldg(p0 + q);
        float4 it0 = __ldg(p0 + 16 + q);
        float4 ev0 = __ldg((const float4*)(cur + t0 * D) + q);
        float2 n0 = __ldg(&d_invn[t0]);
        float g0 = gh.x * gt0.x + gh.y * gt0.y + gh.z * gt0.z + gh.w * gt0.w;
        float i0 = ih.x * it0.x + ih.y * it0.y + ih.z * it0.z + ih.w * it0.w;
        #pragma unroll
        for (int o = 8; o >= 1; o >>= 1) {
            g0 += __shfl_xor_sync(hmask, g0, o);
            i0 += __shfl_xor_sync(hmask, i0, o);
        }
        float ag0 = (g0 * ng * n0.x + 1.0f) * 0.5f;
        float ai0 = (i0 * ni * n0.y + 1.0f) * 0.5f;
        rsg += ag0;
        rsi += ai0;
        accg.x += ag0 * ev0.x; accg.y += ag0 * ev0.y;
        accg.z += ag0 * ev0.z; accg.w += ag0 * ev0.w;
        acci.x += ai0 * ev0.x; acci.y += ai0 * ev0.y;
        acci.z += ai0 * ev0.z; acci.w += ai0 * ev0.w;
    }

    // combine halves (warp reconverged)
    rsg += __shfl_xor_sync(0xffffffffu, rsg, 16);
    rsi += __shfl_xor_sync(0xffffffffu, rsi, 16);
    accg.x += __shfl_xor_sync(0xffffffffu, accg.x, 16);
    accg.y += __shfl_xor_sync(0xffffffffu, accg.y, 16);
    accg.z += __shfl_xor_sync(0xffffffffu, accg.z, 16);
    accg.w += __shfl_xor_sync(0xffffffffu, accg.w, 16);
    acci.x += __shfl_xor_sync(0xffffffffu, acci.x, 16);
    acci.y += __shfl_xor_sync(0xffffffffu, acci.y, 16);
    acci.z += __shfl_xor_sync(0xffffffffu, acci.z, 16);
    acci.w += __shfl_xor_sync(0xffffffffu, acci.w, 16);

    float dg = (rsg > 0.f) ? (1.0f / rsg) : 0.f;
    float di = (rsi > 0.f) ? (1.0f / rsi) : 0.f;

    if (half == 0) {
        float4 e0 = __ldg((const float4*)(cur + n * D) + q);
        float4 nv;
        nv.x = gh.x + ih.x + dg * accg.x + di * acci.x + e0.x;
        nv.y = gh.y + ih.y + dg * accg.y + di * acci.y + e0.y;
        nv.z = gh.z + ih.z + dg * accg.z + di * acci.z + e0.z;
        nv.w = gh.w + ih.w + dg * accg.w + di * acci.w + e0.w;
        ((float4*)(newe + n * D))[q] = nv;
        float4 ov = ((float4*)(out + n * D))[q];
        ov.x += nv.x; ov.y += nv.y; ov.z += nv.z; ov.w += nv.w;
        ((float4*)(out + n * D))[q] = ov;
    }
}

// ---------------------------------------------------------------------------
extern "C" void kernel_launch(void* const* d_in, const int* in_sizes, int n_in,
                              void* d_out, int out_size) {
    const float* ue = (const float*)d_in[0];
    const float* ie = (const float*)d_in[1];
    const float* uW = (const float*)d_in[2];
    const float* iW = (const float*)d_in[3];
    const int*   h  = (const int*)d_in[4];
    const int*   t  = (const int*)d_in[5];
    float* out = (float*)d_out;

    const int TB = 256;
    const int n4   = NN * D / 4;
    const int gN4  = (n4 + TB - 1) / TB;
    const int gNN  = (NN + TB - 1) / TB;
    const int gE   = (NE + TB - 1) / TB;
    const int gNW  = (NN * 32 + TB - 1) / TB;   // warp-per-node

    float *embA, *embB;
    cudaGetSymbolAddress((void**)&embA, d_embA);
    cudaGetSymbolAddress((void**)&embB, d_embB);

    k_init<<<gN4, TB>>>(ue, ie, out);
    k_cnt_zero<<<gNN, TB>>>();
    k_cnt<<<gE, TB>>>(h);
    k_blocksum<<<NBLK, SCAN_TB>>>();
    k_scanblk<<<1, 1024>>>();
    k_rowptr<<<NBLK, SCAN_TB>>>();
    k_csr<<<gE, TB>>>(h, t);

    float* cur = embA;
    float* nxt = embB;
    for (int layer = 0; layer < NL; layer++) {
        k_spmm_gnn<<<gNW, TB>>>(cur);
        k_intent<<<NN / 8, TB>>>(cur, uW, iW);
        k_adaptive<<<gNW, TB>>>(cur, nxt, out);
        float* tmp = cur; cur = nxt; nxt = tmp;
    }
}

// round 7
// speedup vs baseline: 1.6760x; 1.1055x over previous
#include <cuda_runtime.h>
#include <cuda_fp16.h>
#include <math.h>

#define NU 50000
#define NI 100000
#define NN 150000
#define D  64
#define NINT 128
#define NE 3000000
#define NL 2
#define SCAN_TB 256
#define NBLK ((NN + SCAN_TB - 1) / SCAN_TB)   // 586

// ---------------- scratch (device globals) ----------------------------------
__device__ __align__(256) float d_embA[NN * D];
__device__ __align__(256) float d_embB[NN * D];
__device__ __align__(256) float d_gnn[NN * D];
__device__ __align__(256) float d_int[NN * D];
__device__ __align__(256) float d_scaled[NN * D];   // dis[n] * emb[n]
// packed normalized rows, fp16: chunk q (16B) = { g[4q..4q+3], i[4q..4q+3] }
__device__ __align__(256) __half d_nrm[NN * 2 * D];
__device__ __align__(256) float d_dis[NN];
__device__ __align__(256) int   d_cnt[NN];
__device__ __align__(256) int   d_rowptr[NN + 1];
__device__ __align__(256) int   d_fill[NN];
__device__ __align__(256) int   d_csr_t[NE];
__device__ __align__(256) int   d_blksum[NBLK];

// ---------------------------------------------------------------------------
__global__ void k_init(const float* __restrict__ ue, const float* __restrict__ ie,
                       float* __restrict__ out) {
    int i = blockIdx.x * blockDim.x + threadIdx.x;
    const int n4  = NN * D / 4;
    const int nu4 = NU * D / 4;
    if (i >= n4) return;
    float4 v = (i < nu4) ? ((const float4*)ue)[i] : ((const float4*)ie)[i - nu4];
    ((float4*)d_embA)[i] = v;
    ((float4*)out)[i]    = v;
}

__global__ void k_cnt_zero() {
    int i = blockIdx.x * blockDim.x + threadIdx.x;
    if (i < NN) d_cnt[i] = 0;
}

__global__ void k_cnt(const int* __restrict__ h) {
    int e = blockIdx.x * blockDim.x + threadIdx.x;
    if (e < NE) atomicAdd(&d_cnt[h[e]], 1);
}

__global__ void k_blocksum() {
    __shared__ int sh[SCAN_TB];
    int i = blockIdx.x * SCAN_TB + threadIdx.x;
    int v = (i < NN) ? d_cnt[i] : 0;
    sh[threadIdx.x] = v;
    __syncthreads();
    for (int off = SCAN_TB / 2; off > 0; off >>= 1) {
        if (threadIdx.x < off) sh[threadIdx.x] += sh[threadIdx.x + off];
        __syncthreads();
    }
    if (threadIdx.x == 0) d_blksum[blockIdx.x] = sh[0];
}

__global__ void k_scanblk() {
    __shared__ int sh[1024];
    int tid = threadIdx.x;
    sh[tid] = (tid < NBLK) ? d_blksum[tid] : 0;
    __syncthreads();
    for (int off = 1; off < 1024; off <<= 1) {
        int v = (tid >= off) ? sh[tid - off] : 0;
        __syncthreads();
        sh[tid] += v;
        __syncthreads();
    }
    if (tid < NBLK) d_blksum[tid] = (tid > 0) ? sh[tid - 1] : 0;
    if (tid == 0) d_rowptr[NN] = sh[1023];
}

__global__ void k_rowptr() {
    __shared__ int sh[SCAN_TB];
    int i = blockIdx.x * SCAN_TB + threadIdx.x;
    int c = (i < NN) ? d_cnt[i] : 0;
    sh[threadIdx.x] = c;
    __syncthreads();
    for (int off = 1; off < SCAN_TB; off <<= 1) {
        int v = (threadIdx.x >= off) ? sh[threadIdx.x - off] : 0;
        __syncthreads();
        sh[threadIdx.x] += v;
        __syncthreads();
    }
    if (i < NN) {
        int excl = sh[threadIdx.x] - c + d_blksum[blockIdx.x];
        d_rowptr[i] = excl;
        d_dis[i]  = (c > 0) ? rsqrtf((float)c) : 0.0f;
        d_fill[i] = 0;
    }
}

__global__ void k_csr(const int* __restrict__ h, const int* __restrict__ t) {
    int e = blockIdx.x * blockDim.x + threadIdx.x;
    if (e >= NE) return;
    int hh = h[e];
    int pos = d_rowptr[hh] + atomicAdd(&d_fill[hh], 1);
    d_csr_t[pos] = t[e];
}

// d_scaled = dis[n] * embA  (initial layer)
__global__ void k_scale0() {
    int i = blockIdx.x * blockDim.x + threadIdx.x;
    const int n4 = NN * D / 4;
    if (i >= n4) return;
    float s = d_dis[i >> 4];
    float4 v = ((const float4*)d_embA)[i];
    v.x *= s; v.y *= s; v.z *= s; v.w *= s;
    ((float4*)d_scaled)[i] = v;
}

// warp per node, 16 lanes/edge, 2 edges per half-iter (4 edges in flight).
// gnn[n] = dis[n] * sum_t scaled[t] ; writes f32 row + fp16 normalized g-part.
__global__ void k_spmm_gnn() {
    int n = (blockIdx.x * blockDim.x + threadIdx.x) >> 5;
    int lane = threadIdx.x & 31;
    if (n >= NN) return;
    int half = lane >> 4;
    int q    = lane & 15;
    float dh = d_dis[n];
    float4 a0 = make_float4(0.f, 0.f, 0.f, 0.f);
    float4 a1 = make_float4(0.f, 0.f, 0.f, 0.f);
    int b = d_rowptr[n], e = d_rowptr[n + 1];
    int i = b + half;
    for (; i + 2 < e; i += 4) {
        int t0 = __ldg(&d_csr_t[i]);
        int t1 = __ldg(&d_csr_t[i + 2]);
        float4 r0 = __ldg((const float4*)(d_scaled + t0 * D) + q);
        float4 r1 = __ldg((const float4*)(d_scaled + t1 * D) + q);
        a0.x += r0.x; a0.y += r0.y; a0.z += r0.z; a0.w += r0.w;
        a1.x += r1.x; a1.y += r1.y; a1.z += r1.z; a1.w += r1.w;
    }
    for (; i < e; i += 2) {
        int t0 = __ldg(&d_csr_t[i]);
        float4 r0 = __ldg((const float4*)(d_scaled + t0 * D) + q);
        a0.x += r0.x; a0.y += r0.y; a0.z += r0.z; a0.w += r0.w;
    }
    a0.x = dh * (a0.x + a1.x); a0.y = dh * (a0.y + a1.y);
    a0.z = dh * (a0.z + a1.z); a0.w = dh * (a0.w + a1.w);
    a0.x += __shfl_xor_sync(0xffffffffu, a0.x, 16);
    a0.y += __shfl_xor_sync(0xffffffffu, a0.y, 16);
    a0.z += __shfl_xor_sync(0xffffffffu, a0.z, 16);
    a0.w += __shfl_xor_sync(0xffffffffu, a0.w, 16);
    float sg = a0.x * a0.x + a0.y * a0.y + a0.z * a0.z + a0.w * a0.w;
    #pragma unroll
    for (int o = 8; o >= 1; o >>= 1) sg += __shfl_xor_sync(0xffffffffu, sg, o);
    float s = 1.0f / fmaxf(sqrtf(sg), 1e-8f);
    if (half == 0) {
        ((float4*)(d_gnn + n * D))[q] = a0;
        __half2 p0 = __floats2half2_rn(a0.x * s, a0.y * s);
        __half2 p1 = __floats2half2_rn(a0.z * s, a0.w * s);
        uint2 u;
        u.x = *(unsigned*)&p0;
        u.y = *(unsigned*)&p1;
        *(uint2*)(d_nrm + n * 2 * D + 8 * q) = u;   // g-part of chunk q
    }
}

// warp-per-row softmax-intent projection; writes f32 row + fp16 normalized i-part.
__global__ void k_intent(const float* __restrict__ cur,
                         const float* __restrict__ uW, const float* __restrict__ iW) {
    __shared__ float WT[NINT][D + 1];
    __shared__ float rowbuf[8][D];
    int wid = threadIdx.x >> 5, lane = threadIdx.x & 31;
    int row0 = blockIdx.x * 8;
    const float* W = (row0 < NU) ? uW : iW;
    for (int idx = threadIdx.x; idx < D * NINT; idx += blockDim.x) {
        int dd = idx / NINT, j = idx % NINT;
        WT[j][dd] = W[idx];
    }
    __syncthreads();
    int row = row0 + wid;
    if (row >= NN) return;
    const float* src = cur + row * D;
    rowbuf[wid][lane]      = src[lane];
    rowbuf[wid][lane + 32] = src[lane + 32];
    __syncwarp();

    float lg[4] = {0.f, 0.f, 0.f, 0.f};
    #pragma unroll
    for (int dd = 0; dd < D; dd++) {
        float rb = rowbuf[wid][dd];
        #pragma unroll
        for (int s = 0; s < 4; s++) lg[s] += rb * WT[s * 32 + lane][dd];
    }
    float m = fmaxf(fmaxf(lg[0], lg[1]), fmaxf(lg[2], lg[3]));
    #pragma unroll
    for (int o = 16; o >= 1; o >>= 1) m = fmaxf(m, __shfl_xor_sync(0xffffffffu, m, o));
    float p[4], ssum = 0.f;
    #pragma unroll
    for (int s = 0; s < 4; s++) { p[s] = expf(lg[s] - m); ssum += p[s]; }
    #pragma unroll
    for (int o = 16; o >= 1; o >>= 1) ssum += __shfl_xor_sync(0xffffffffu, ssum, o);
    float inv = 1.0f / ssum;
    #pragma unroll
    for (int s = 0; s < 4; s++) p[s] *= inv;

    float o0 = 0.f, o1 = 0.f;
    #pragma unroll
    for (int s = 0; s < 4; s++) {
        #pragma unroll
        for (int l = 0; l < 32; l++) {
            float pv = __shfl_sync(0xffffffffu, p[s], l);
            int j = s * 32 + l;
            o0 += pv * WT[j][lane];
            o1 += pv * WT[j][lane + 32];
        }
    }
    d_int[row * D + lane]      = o0;
    d_int[row * D + lane + 32] = o1;
    float si = o0 * o0 + o1 * o1;
    #pragma unroll
    for (int o = 16; o >= 1; o >>= 1) si += __shfl_xor_sync(0xffffffffu, si, o);
    si = __shfl_sync(0xffffffffu, si, 0);
    float s = 1.0f / fmaxf(sqrtf(si), 1e-8f);
    // i-part of packed nrm: dim d -> index 8*(d/4) + 4 + (d%4)
    int d0 = lane, d1 = lane + 32;
    d_nrm[row * 2 * D + 8 * (d0 >> 2) + 4 + (d0 & 3)] = __float2half_rn(o0 * s);
    d_nrm[row * 2 * D + 8 * (d1 >> 2) + 4 + (d1 & 3)] = __float2half_rn(o1 * s);
}

// fused adaptive pass, warp per node, 16 lanes/edge, unrolled 2x per half.
// Alphas from fp16 pre-normalized rows: one LDG.128/edge-lane covers both dots.
__global__ void k_adaptive(const float* __restrict__ cur, float* __restrict__ newe,
                           float* __restrict__ out) {
    int n = (blockIdx.x * blockDim.x + threadIdx.x) >> 5;
    int lane = threadIdx.x & 31;
    if (n >= NN) return;
    int half = lane >> 4;
    int q    = lane & 15;
    unsigned hmask = half ? 0xFFFF0000u : 0x0000FFFFu;
    int b = d_rowptr[n], e = d_rowptr[n + 1];

    // h-side normalized chunk
    uint4 hv = __ldg((const uint4*)(d_nrm + n * 2 * D) + q);
    float2 gh01 = __half22float2(*(__half2*)&hv.x);
    float2 gh23 = __half22float2(*(__half2*)&hv.y);
    float2 ih01 = __half22float2(*(__half2*)&hv.z);
    float2 ih23 = __half22float2(*(__half2*)&hv.w);

    float rsg = 0.f, rsi = 0.f;
    float4 accg = make_float4(0.f, 0.f, 0.f, 0.f);
    float4 acci = make_float4(0.f, 0.f, 0.f, 0.f);

    int i = b + half;
    for (; i + 2 < e; i += 4) {
        int t0 = __ldg(&d_csr_t[i]);
        int t1 = __ldg(&d_csr_t[i + 2]);
        uint4 v0 = __ldg((const uint4*)(d_nrm + t0 * 2 * D) + q);
        uint4 v1 = __ldg((const uint4*)(d_nrm + t1 * 2 * D) + q);
        float4 ev0 = __ldg((const float4*)(cur + t0 * D) + q);
        float4 ev1 = __ldg((const float4*)(cur + t1 * D) + q);

        float2 a, c;
        a = __half22float2(*(__half2*)&v0.x); c = __half22float2(*(__half2*)&v0.y);
        float g0 = gh01.x * a.x + gh01.y * a.y + gh23.x * c.x + gh23.y * c.y;
        a = __half22float2(*(__half2*)&v0.z); c = __half22float2(*(__half2*)&v0.w);
        float i0 = ih01.x * a.x + ih01.y * a.y + ih23.x * c.x + ih23.y * c.y;
        a = __half22float2(*(__half2*)&v1.x); c = __half22float2(*(__half2*)&v1.y);
        float g1 = gh01.x * a.x + gh01.y * a.y + gh23.x * c.x + gh23.y * c.y;
        a = __half22float2(*(__half2*)&v1.z); c = __half22float2(*(__half2*)&v1.w);
        float i1 = ih01.x * a.x + ih01.y * a.y + ih23.x * c.x + ih23.y * c.y;

        #pragma unroll
        for (int o = 8; o >= 1; o >>= 1) {
            g0 += __shfl_xor_sync(hmask, g0, o);
            i0 += __shfl_xor_sync(hmask, i0, o);
            g1 += __shfl_xor_sync(hmask, g1, o);
            i1 += __shfl_xor_sync(hmask, i1, o);
        }
        float ag0 = (g0 + 1.0f) * 0.5f;
        float ai0 = (i0 + 1.0f) * 0.5f;
        float ag1 = (g1 + 1.0f) * 0.5f;
        float ai1 = (i1 + 1.0f) * 0.5f;
        rsg += ag0 + ag1;
        rsi += ai0 + ai1;
        accg.x += ag0 * ev0.x + ag1 * ev1.x;
        accg.y += ag0 * ev0.y + ag1 * ev1.y;
        accg.z += ag0 * ev0.z + ag1 * ev1.z;
        accg.w += ag0 * ev0.w + ag1 * ev1.w;
        acci.x += ai0 * ev0.x + ai1 * ev1.x;
        acci.y += ai0 * ev0.y + ai1 * ev1.y;
        acci.z += ai0 * ev0.z + ai1 * ev1.z;
        acci.w += ai0 * ev0.w + ai1 * ev1.w;
    }
    for (; i < e; i += 2) {
        int t0 = __ldg(&d_csr_t[i]);
        uint4 v0 = __ldg((const uint4*)(d_nrm + t0 * 2 * D) + q);
        float4 ev0 = __ldg((const float4*)(cur + t0 * D) + q);
        float2 a, c;
        a = __half22float2(*(__half2*)&v0.x); c = __half22float2(*(__half2*)&v0.y);
        float g0 = gh01.x * a.x + gh01.y * a.y + gh23.x * c.x + gh23.y * c.y;
        a = __half22float2(*(__half2*)&v0.z); c = __half22float2(*(__half2*)&v0.w);
        float i0 = ih01.x * a.x + ih01.y * a.y + ih23.x * c.x + ih23.y * c.y;
        #pragma unroll
        for (int o = 8; o >= 1; o >>= 1) {
            g0 += __shfl_xor_sync(hmask, g0, o);
            i0 += __shfl_xor_sync(hmask, i0, o);
        }
        float ag0 = (g0 + 1.0f) * 0.5f;
        float ai0 = (i0 + 1.0f) * 0.5f;
        rsg += ag0;
        rsi += ai0;
        accg.x += ag0 * ev0.x; accg.y += ag0 * ev0.y;
        accg.z += ag0 * ev0.z; accg.w += ag0 * ev0.w;
        acci.x += ai0 * ev0.x; acci.y += ai0 * ev0.y;
        acci.z += ai0 * ev0.z; acci.w += ai0 * ev0.w;
    }

    // combine halves (warp reconverged)
    rsg += __shfl_xor_sync(0xffffffffu, rsg, 16);
    rsi += __shfl_xor_sync(0xffffffffu, rsi, 16);
    accg.x += __shfl_xor_sync(0xffffffffu, accg.x, 16);
    accg.y += __shfl_xor_sync(0xffffffffu, accg.y, 16);
    accg.z += __shfl_xor_sync(0xffffffffu, accg.z, 16);
    accg.w += __shfl_xor_sync(0xffffffffu, accg.w, 16);
    acci.x += __shfl_xor_sync(0xffffffffu, acci.x, 16);
    acci.y += __shfl_xor_sync(0xffffffffu, acci.y, 16);
    acci.z += __shfl_xor_sync(0xffffffffu, acci.z, 16);
    acci.w += __shfl_xor_sync(0xffffffffu, acci.w, 16);

    float dg = (rsg > 0.f) ? (1.0f / rsg) : 0.f;
    float di = (rsi > 0.f) ? (1.0f / rsi) : 0.f;

    if (half == 0) {
        float4 gh4 = __ldg((const float4*)(d_gnn + n * D) + q);
        float4 ih4 = __ldg((const float4*)(d_int + n * D) + q);
        float4 e0  = __ldg((const float4*)(cur   + n * D) + q);
        float4 nv;
        nv.x = gh4.x + ih4.x + dg * accg.x + di * acci.x + e0.x;
        nv.y = gh4.y + ih4.y + dg * accg.y + di * acci.y + e0.y;
        nv.z = gh4.z + ih4.z + dg * accg.z + di * acci.z + e0.z;
        nv.w = gh4.w + ih4.w + dg * accg.w + di * acci.w + e0.w;
        ((float4*)(newe + n * D))[q] = nv;
        float4 ov = ((float4*)(out + n * D))[q];
        ov.x += nv.x; ov.y += nv.y; ov.z += nv.z; ov.w += nv.w;
        ((float4*)(out + n * D))[q] = ov;
        // pre-scaled embedding for next layer's gnn SpMM
        float ds = d_dis[n];
        float4 sv = make_float4(ds * nv.x, ds * nv.y, ds * nv.z, ds * nv.w);
        ((float4*)(d_scaled + n * D))[q] = sv;
    }
}

// ---------------------------------------------------------------------------
extern "C" void kernel_launch(void* const* d_in, const int* in_sizes, int n_in,
                              void* d_out, int out_size) {
    const float* ue = (const float*)d_in[0];
    const float* ie = (const float*)d_in[1];
    const float* uW = (const float*)d_in[2];
    const float* iW = (const float*)d_in[3];
    const int*   h  = (const int*)d_in[4];
    const int*   t  = (const int*)d_in[5];
    float* out = (float*)d_out;

    const int TB = 256;
    const int n4   = NN * D / 4;
    const int gN4  = (n4 + TB - 1) / TB;
    const int gNN  = (NN + TB - 1) / TB;
    const int gE   = (NE + TB - 1) / TB;
    const int gNW  = (NN * 32 + TB - 1) / TB;   // warp-per-node

    float *embA, *embB;
    cudaGetSymbolAddress((void**)&embA, d_embA);
    cudaGetSymbolAddress((void**)&embB, d_embB);

    k_init<<<gN4, TB>>>(ue, ie, out);
    k_cnt_zero<<<gNN, TB>>>();
    k_cnt<<<gE, TB>>>(h);
    k_blocksum<<<NBLK, SCAN_TB>>>();
    k_scanblk<<<1, 1024>>>();
    k_rowptr<<<NBLK, SCAN_TB>>>();
    k_csr<<<gE, TB>>>(h, t);
    k_scale0<<<gN4, TB>>>();

    float* cur = embA;
    float* nxt = embB;
    for (int layer = 0; layer < NL; layer++) {
        k_spmm_gnn<<<gNW, TB>>>();
        k_intent<<<NN / 8, TB>>>(cur, uW, iW);
        k_adaptive<<<gNW, TB>>>(cur, nxt, out);
        float* tmp = cur; cur = nxt; nxt = tmp;
    }
}